// round 2
// baseline (speedup 1.0000x reference)
#include <cuda_runtime.h>

#define NN 50000
#define FF 16
#define EE 800000
#define HH 64
#define TOUT 10
#define NF (NN*FF)

// ---------------- device state ----------------
__device__ float g_x0[NF];
__device__ float g_xi[NF];
__device__ float g_k[6][NF];
__device__ float g_u[NN*HH];
__device__ float g_v[NN*HH];
__device__ float g_augproj[NN*HH];
__device__ float g_ys[TOUT*NF];
__device__ int   g_deg[NN];
__device__ int   g_rowptr[NN+1];
__device__ int   g_wptr[NN];
__device__ int   g_src_sorted[EE];
__device__ float4 g_ea_sorted[EE];

// DOPRI5 coefficients. Row 0 unused (stage 0), rows 1..5 = A[0..4], row 6 = B.
__constant__ float c_coef[7][6] = {
  {0.f,0.f,0.f,0.f,0.f,0.f},
  {(float)(0.2), 0.f,0.f,0.f,0.f,0.f},
  {(float)(3.0/40.0), (float)(9.0/40.0), 0.f,0.f,0.f,0.f},
  {(float)(44.0/45.0), (float)(-56.0/15.0), (float)(32.0/9.0), 0.f,0.f,0.f},
  {(float)(19372.0/6561.0), (float)(-25360.0/2187.0), (float)(64448.0/6561.0), (float)(-212.0/729.0), 0.f,0.f},
  {(float)(9017.0/3168.0), (float)(-355.0/33.0), (float)(46732.0/5247.0), (float)(49.0/176.0), (float)(-5103.0/18656.0), 0.f},
  {(float)(35.0/384.0), 0.f, (float)(500.0/1113.0), (float)(125.0/192.0), (float)(-2187.0/6784.0), (float)(11.0/84.0)}
};
__constant__ float c_C[6] = {0.f, 0.2f, 0.3f, 0.8f, (float)(8.0/9.0), 1.f};

__device__ __forceinline__ float tanh_fast(float x) {
  float ax = fabsf(x);
  float e  = __expf(-2.0f * ax);
  float r  = __fdividef(1.0f - e, 1.0f + e);
  return copysignf(r, x);
}

// ---------------- once-per-launch setup ----------------

// aug features + projection through W1n rows [32,208) with b1n folded in.
__global__ __launch_bounds__(256) void augproj_kernel(
    const float* __restrict__ xh, const float* __restrict__ xm,
    const float* __restrict__ W1n, const float* __restrict__ b1n)
{
  __shared__ float saug[4][176];
  int tid = threadIdx.x;
  int ln = tid >> 6;          // local node 0..3
  int ch = tid & 63;
  int n = blockIdx.x * 4 + ln;
  if (ch < 16) {
    int f = ch;
    float xs[10], ms[10];
    float sm = 0.f, cm = 0.f;
    #pragma unroll
    for (int tt = 0; tt < 10; tt++) {
      xs[tt] = xh[(tt * NN + n) * FF + f];
      ms[tt] = xm[tt * NN + n];
      sm += xs[tt] * ms[tt];
      cm += ms[tt];
    }
    float cnt = fmaxf(cm, 1.0f);
    float mean = sm / cnt;
    float var = 0.f;
    #pragma unroll
    for (int tt = 0; tt < 10; tt++) { float d = xs[tt] - mean; var += d * d * ms[tt]; }
    var /= cnt;
    #pragma unroll
    for (int tt = 0; tt < 9; tt++)
      saug[ln][tt * 16 + f] = (xs[tt + 1] - xs[tt]) * (ms[tt + 1] * ms[tt]);
    saug[ln][144 + f] = mean;
    saug[ln][160 + f] = var;
  }
  __syncthreads();
  float acc = b1n[ch];
  #pragma unroll 8
  for (int r = 0; r < 176; r++)
    acc += saug[ln][r] * W1n[(32 + r) * 64 + ch];
  g_augproj[n * 64 + ch] = acc;
}

__global__ __launch_bounds__(256) void copyx0_kernel(const float* __restrict__ xh) {
  int i = blockIdx.x * 256 + threadIdx.x;
  if (i < NF) g_x0[i] = xh[9 * NF + i];
}

__global__ __launch_bounds__(256) void zero_deg_kernel() {
  int i = blockIdx.x * 256 + threadIdx.x;
  if (i < NN) g_deg[i] = 0;
}

__global__ __launch_bounds__(256) void hist_kernel(const int* __restrict__ ei) {
  int e = blockIdx.x * 256 + threadIdx.x;
  if (e < EE) atomicAdd(&g_deg[ei[EE + e]], 1);
}

// single-block scan: row_ptr (exclusive into wptr, inclusive into rowptr[i+1])
__global__ __launch_bounds__(1024) void scan_kernel() {
  __shared__ int wsum[32];
  int tid = threadIdx.x, lane = tid & 31, wid = tid >> 5;
  int carry = 0;
  for (int base = 0; base < NN; base += 1024) {
    int i = base + tid;
    int v = (i < NN) ? g_deg[i] : 0;
    int x = v;
    #pragma unroll
    for (int o = 1; o < 32; o <<= 1) { int y = __shfl_up_sync(0xffffffffu, x, o); if (lane >= o) x += y; }
    if (lane == 31) wsum[wid] = x;
    __syncthreads();
    if (wid == 0) {
      int s = wsum[lane];
      #pragma unroll
      for (int o = 1; o < 32; o <<= 1) { int y = __shfl_up_sync(0xffffffffu, s, o); if (lane >= o) s += y; }
      wsum[lane] = s;
    }
    __syncthreads();
    int incl = x + carry + (wid > 0 ? wsum[wid - 1] : 0);
    if (i < NN) { g_rowptr[i + 1] = incl; g_wptr[i] = incl - v; }
    carry += wsum[31];
    __syncthreads();
  }
  if (tid == 0) g_rowptr[0] = 0;
}

__global__ __launch_bounds__(256) void scatter_kernel(
    const int* __restrict__ ei, const float* __restrict__ ea)
{
  int e = blockIdx.x * 256 + threadIdx.x;
  if (e < EE) {
    int d = ei[EE + e];
    int pos = atomicAdd(&g_wptr[d], 1);
    g_src_sorted[pos] = ei[e];
    g_ea_sorted[pos] = ((const float4*)ea)[e];
  }
}

// ---------------- per-stage kernels ----------------

// pre: combine RK state xi = x0 + dti * sum(coef_j * k_j); project u = xi@W1m[0:16],
// v = xi@W1m[16:32] + b1m. s==0: xi=x0. s==6: writes new x0 (and output row).
__global__ __launch_bounds__(512) void pre_kernel(
    const float* __restrict__ t, int it, int s, int outrow,
    const float* __restrict__ W1m, const float* __restrict__ b1m)
{
  __shared__ float sW[32 * 64];
  __shared__ float sxi[8][16];
  int tid = threadIdx.x;
  #pragma unroll
  for (int i = tid; i < 2048; i += 512) sW[i] = W1m[i];
  int ln = tid >> 6;            // local node 0..7
  int ch = tid & 63;
  int node = blockIdx.x * 8 + ln;
  if (ch < 16) {
    int idx = node * 16 + ch;
    float xv = g_x0[idx];
    if (s >= 1) {
      float dti = (t[it + 1] - t[it]) * 0.25f;
      int nk = (s == 6) ? 6 : s;
      float acc = 0.f;
      for (int j = 0; j < nk; j++) acc += c_coef[s][j] * g_k[j][idx];
      xv += dti * acc;
    }
    if (s == 6) {
      g_x0[idx] = xv;
      if (outrow >= 0) g_ys[outrow * NF + idx] = xv;
    }
    g_xi[idx] = xv;
    sxi[ln][ch] = xv;
  }
  __syncthreads();
  const float* x = sxi[ln];
  float u = 0.f, v = b1m[ch];
  #pragma unroll
  for (int i = 0; i < 16; i++) {
    u += x[i] * sW[i * 64 + ch];
    v += x[i] * sW[(16 + i) * 64 + ch];
  }
  g_u[node * 64 + ch] = u;
  g_v[node * 64 + ch] = v;
}

// fused edge accumulation (warp per dst node, CSR) + node MLP -> k[s]
__global__ __launch_bounds__(256) void edge_node_kernel(
    int s, int it, int sub,
    const float* __restrict__ t,
    const float* __restrict__ W1m, const float* __restrict__ W2m,
    const float* __restrict__ b2m, const float* __restrict__ W1n,
    const float* __restrict__ W2n, const float* __restrict__ b2n)
{
  __shared__ float sWea[4 * 64];
  __shared__ float sW2m[64 * 16];
  __shared__ float sW1nx[16 * 64];
  __shared__ float sW1na[16 * 64];
  __shared__ float sW2n[64 * 16];
  __shared__ float swt[64];
  __shared__ float sb2m[16], sb2n[16];
  __shared__ float sbuf[8][64];
  __shared__ float sxi[8][16];
  __shared__ float sagg[8][16];

  int tid = threadIdx.x;
  for (int i = tid; i < 256; i += 256) sWea[i] = W1m[32 * 64 + i];
  for (int i = tid; i < 1024; i += 256) {
    sW2m[i]  = W2m[i];
    sW1nx[i] = W1n[i];
    sW1na[i] = W1n[1024 + i];
    sW2n[i]  = W2n[i];
  }
  if (tid < 64) swt[tid] = W1n[208 * 64 + tid];
  if (tid < 16) { sb2m[tid] = b2m[tid]; sb2n[tid] = b2n[tid]; }

  int w = tid >> 5, lane = tid & 31;
  int n = blockIdx.x * 8 + w;
  if (lane < 16) sxi[w][lane] = g_xi[n * 16 + lane];
  __syncthreads();

  float tA = t[it], tB = t[it + 1];
  float dti = (tB - tA) * 0.25f;
  float ti = tA + (float)sub * dti + c_C[s] * dti;

  float v0 = g_v[n * 64 + lane];
  float v1 = g_v[n * 64 + 32 + lane];
  float acc0 = 0.f, acc1 = 0.f;
  int beg = g_rowptr[n], end = g_rowptr[n + 1];
  for (int e = beg; e < end; e++) {
    int src = g_src_sorted[e];
    float4 ea = g_ea_sorted[e];
    const float* ub = &g_u[src * 64];
    float a0 = ub[lane] + v0;
    float a1 = ub[32 + lane] + v1;
    a0 += ea.x * sWea[lane]       + ea.y * sWea[64 + lane]
        + ea.z * sWea[128 + lane] + ea.w * sWea[192 + lane];
    a1 += ea.x * sWea[32 + lane]       + ea.y * sWea[64 + 32 + lane]
        + ea.z * sWea[128 + 32 + lane] + ea.w * sWea[192 + 32 + lane];
    acc0 += tanh_fast(a0);
    acc1 += tanh_fast(a1);
  }

  // agg16 = hsum @ W2m + deg*b2m
  sbuf[w][lane] = acc0;
  sbuf[w][32 + lane] = acc1;
  __syncwarp();
  int j = lane & 15;
  int cbase = (lane < 16) ? 0 : 32;
  float p = 0.f;
  #pragma unroll
  for (int c = 0; c < 32; c++) p += sbuf[w][cbase + c] * sW2m[(cbase + c) * 16 + j];
  p += __shfl_xor_sync(0xffffffffu, p, 16);
  float degf = (float)(end - beg);
  if (lane < 16) sagg[w][lane] = p + degf * sb2m[j];
  __syncwarp();

  // hidden = xi@W1n_x + agg@W1n_agg + aug_proj + ti*wt
  float h0 = g_augproj[n * 64 + lane]      + ti * swt[lane];
  float h1 = g_augproj[n * 64 + 32 + lane] + ti * swt[32 + lane];
  #pragma unroll
  for (int i = 0; i < 16; i++) {
    float xv = sxi[w][i], av = sagg[w][i];
    h0 += xv * sW1nx[i * 64 + lane]      + av * sW1na[i * 64 + lane];
    h1 += xv * sW1nx[i * 64 + 32 + lane] + av * sW1na[i * 64 + 32 + lane];
  }
  __syncwarp();
  sbuf[w][lane] = tanh_fast(h0);
  sbuf[w][32 + lane] = tanh_fast(h1);
  __syncwarp();

  float o = 0.f;
  #pragma unroll
  for (int c = 0; c < 32; c++) o += sbuf[w][cbase + c] * sW2n[(cbase + c) * 16 + j];
  o += __shfl_xor_sync(0xffffffffu, o, 16);
  if (lane < 16) g_k[s][n * 16 + j] = o + sb2n[j];
}

__global__ __launch_bounds__(256) void gather_out_kernel(
    const int* __restrict__ mask_idx, float* __restrict__ out)
{
  int idx = blockIdx.x * 256 + threadIdx.x;
  if (idx < TOUT * NF) {
    int row = idx / NF;
    int rem = idx - row * NF;
    out[idx] = g_ys[mask_idx[row] * NF + rem];
  }
}

// ---------------- launcher ----------------
extern "C" void kernel_launch(void* const* d_in, const int* in_sizes, int n_in,
                              void* d_out, int out_size)
{
  const float* x_hist   = (const float*)d_in[0];
  const float* x_mask   = (const float*)d_in[1];
  const int*   ei       = (const int*)d_in[2];
  const float* ea       = (const float*)d_in[3];
  const float* t        = (const float*)d_in[4];
  const int*   mask_idx = (const int*)d_in[5];
  const float* W1m = (const float*)d_in[6];
  const float* b1m = (const float*)d_in[7];
  const float* W2m = (const float*)d_in[8];
  const float* b2m = (const float*)d_in[9];
  const float* W1n = (const float*)d_in[10];
  const float* b1n = (const float*)d_in[11];
  const float* W2n = (const float*)d_in[12];
  const float* b2n = (const float*)d_in[13];
  float* out = (float*)d_out;

  // once-per-launch preprocessing (amortized over 240 evals)
  augproj_kernel<<<NN / 4, 256>>>(x_hist, x_mask, W1n, b1n);
  copyx0_kernel<<<(NF + 255) / 256, 256>>>(x_hist);
  zero_deg_kernel<<<(NN + 255) / 256, 256>>>();
  hist_kernel<<<(EE + 255) / 256, 256>>>(ei);
  scan_kernel<<<1, 1024>>>();
  scatter_kernel<<<(EE + 255) / 256, 256>>>(ei, ea);

  // initial u,v,xi from x0
  pre_kernel<<<NN / 8, 512>>>(t, 0, 0, -1, W1m, b1m);

  for (int it = 0; it < TOUT; it++) {
    for (int sub = 0; sub < 4; sub++) {
      for (int s = 0; s < 6; s++) {
        edge_node_kernel<<<NN / 8, 256>>>(s, it, sub, t, W1m, W2m, b2m, W1n, W2n, b2n);
        if (s < 5) pre_kernel<<<NN / 8, 512>>>(t, it, s + 1, -1, W1m, b1m);
      }
      int outrow = (sub == 3) ? it : -1;
      // final combine (B row): updates x0 in place, emits output row,
      // and produces u,v,xi for the next step's stage 0.
      pre_kernel<<<NN / 8, 512>>>(t, it, 6, outrow, W1m, b1m);
    }
  }

  gather_out_kernel<<<(TOUT * NF + 255) / 256, 256>>>(mask_idx, out);
}

// round 3
// speedup vs baseline: 1.0023x; 1.0023x over previous
#include <cuda_runtime.h>

#define NN 50000
#define FF 16
#define EE 800000
#define HH 64
#define TOUT 10
#define NF (NN*FF)

// ---------------- device state ----------------
__device__ float g_x0[NF];
__device__ float g_xi[NF];
__device__ float g_k[6][NF];
__device__ float g_u[NN*HH];
__device__ float g_v[NN*HH];
__device__ float g_augproj[NN*HH];
__device__ float g_ys[TOUT*NF];
__device__ int   g_deg[NN];
__device__ int   g_rowptr[NN+1];
__device__ int   g_wptr[NN];
__device__ int   g_src_sorted[EE];
__device__ float4 g_ea_sorted[EE];

// DOPRI5 coefficients. Row 0 unused (stage 0), rows 1..5 = A[0..4], row 6 = B.
__constant__ float c_coef[7][6] = {
  {0.f,0.f,0.f,0.f,0.f,0.f},
  {(float)(0.2), 0.f,0.f,0.f,0.f,0.f},
  {(float)(3.0/40.0), (float)(9.0/40.0), 0.f,0.f,0.f,0.f},
  {(float)(44.0/45.0), (float)(-56.0/15.0), (float)(32.0/9.0), 0.f,0.f,0.f},
  {(float)(19372.0/6561.0), (float)(-25360.0/2187.0), (float)(64448.0/6561.0), (float)(-212.0/729.0), 0.f,0.f},
  {(float)(9017.0/3168.0), (float)(-355.0/33.0), (float)(46732.0/5247.0), (float)(49.0/176.0), (float)(-5103.0/18656.0), 0.f},
  {(float)(35.0/384.0), 0.f, (float)(500.0/1113.0), (float)(125.0/192.0), (float)(-2187.0/6784.0), (float)(11.0/84.0)}
};
__constant__ float c_C[6] = {0.f, 0.2f, 0.3f, 0.8f, (float)(8.0/9.0), 1.f};

__device__ __forceinline__ float tanh_fast(float x) {
  float ax = fabsf(x);
  float e  = __expf(-2.0f * ax);
  float r  = __fdividef(1.0f - e, 1.0f + e);
  return copysignf(r, x);
}

// ---------------- once-per-launch setup ----------------

// aug features + projection through W1n rows [32,208) with b1n folded in.
__global__ __launch_bounds__(256) void augproj_kernel(
    const float* __restrict__ xh, const float* __restrict__ xm,
    const float* __restrict__ W1n, const float* __restrict__ b1n)
{
  __shared__ float saug[4][176];
  int tid = threadIdx.x;
  int ln = tid >> 6;          // local node 0..3
  int ch = tid & 63;
  int n = blockIdx.x * 4 + ln;
  if (ch < 16) {
    int f = ch;
    float xs[10], ms[10];
    float sm = 0.f, cm = 0.f;
    #pragma unroll
    for (int tt = 0; tt < 10; tt++) {
      xs[tt] = xh[(tt * NN + n) * FF + f];
      ms[tt] = xm[tt * NN + n];
      sm += xs[tt] * ms[tt];
      cm += ms[tt];
    }
    float cnt = fmaxf(cm, 1.0f);
    float mean = sm / cnt;
    float var = 0.f;
    #pragma unroll
    for (int tt = 0; tt < 10; tt++) { float d = xs[tt] - mean; var += d * d * ms[tt]; }
    var /= cnt;
    #pragma unroll
    for (int tt = 0; tt < 9; tt++)
      saug[ln][tt * 16 + f] = (xs[tt + 1] - xs[tt]) * (ms[tt + 1] * ms[tt]);
    saug[ln][144 + f] = mean;
    saug[ln][160 + f] = var;
  }
  __syncthreads();
  float acc = b1n[ch];
  #pragma unroll 8
  for (int r = 0; r < 176; r++)
    acc += saug[ln][r] * W1n[(32 + r) * 64 + ch];
  g_augproj[n * 64 + ch] = acc;
}

__global__ __launch_bounds__(256) void copyx0_kernel(const float* __restrict__ xh) {
  int i = blockIdx.x * 256 + threadIdx.x;
  if (i < NF) g_x0[i] = xh[9 * NF + i];
}

__global__ __launch_bounds__(256) void zero_deg_kernel() {
  int i = blockIdx.x * 256 + threadIdx.x;
  if (i < NN) g_deg[i] = 0;
}

__global__ __launch_bounds__(256) void hist_kernel(const int* __restrict__ ei) {
  int e = blockIdx.x * 256 + threadIdx.x;
  if (e < EE) atomicAdd(&g_deg[ei[EE + e]], 1);
}

// single-block scan: row_ptr (exclusive into wptr, inclusive into rowptr[i+1])
__global__ __launch_bounds__(1024) void scan_kernel() {
  __shared__ int wsum[32];
  int tid = threadIdx.x, lane = tid & 31, wid = tid >> 5;
  int carry = 0;
  for (int base = 0; base < NN; base += 1024) {
    int i = base + tid;
    int v = (i < NN) ? g_deg[i] : 0;
    int x = v;
    #pragma unroll
    for (int o = 1; o < 32; o <<= 1) { int y = __shfl_up_sync(0xffffffffu, x, o); if (lane >= o) x += y; }
    if (lane == 31) wsum[wid] = x;
    __syncthreads();
    if (wid == 0) {
      int s = wsum[lane];
      #pragma unroll
      for (int o = 1; o < 32; o <<= 1) { int y = __shfl_up_sync(0xffffffffu, s, o); if (lane >= o) s += y; }
      wsum[lane] = s;
    }
    __syncthreads();
    int incl = x + carry + (wid > 0 ? wsum[wid - 1] : 0);
    if (i < NN) { g_rowptr[i + 1] = incl; g_wptr[i] = incl - v; }
    carry += wsum[31];
    __syncthreads();
  }
  if (tid == 0) g_rowptr[0] = 0;
}

__global__ __launch_bounds__(256) void scatter_kernel(
    const int* __restrict__ ei, const float* __restrict__ ea)
{
  int e = blockIdx.x * 256 + threadIdx.x;
  if (e < EE) {
    int d = ei[EE + e];
    int pos = atomicAdd(&g_wptr[d], 1);
    g_src_sorted[pos] = ei[e];
    g_ea_sorted[pos] = ((const float4*)ea)[e];
  }
}

// ---------------- per-stage kernels ----------------

// pre: combine RK state xi = x0 + dti * sum(coef_j * k_j); project u = xi@W1m[0:16],
// v = xi@W1m[16:32] + b1m. s==0: xi=x0. s==6: writes new x0 (and output row).
__global__ __launch_bounds__(512) void pre_kernel(
    const float* __restrict__ t, int it, int s, int outrow,
    const float* __restrict__ W1m, const float* __restrict__ b1m)
{
  __shared__ float sW[32 * 64];
  __shared__ float sxi[8][16];
  int tid = threadIdx.x;
  #pragma unroll
  for (int i = tid; i < 2048; i += 512) sW[i] = W1m[i];
  int ln = tid >> 6;            // local node 0..7
  int ch = tid & 63;
  int node = blockIdx.x * 8 + ln;
  if (ch < 16) {
    int idx = node * 16 + ch;
    float xv = g_x0[idx];
    if (s >= 1) {
      float dti = (t[it + 1] - t[it]) * 0.25f;
      int nk = (s == 6) ? 6 : s;
      float acc = 0.f;
      for (int j = 0; j < nk; j++) acc += c_coef[s][j] * g_k[j][idx];
      xv += dti * acc;
    }
    if (s == 6) {
      g_x0[idx] = xv;
      if (outrow >= 0) g_ys[outrow * NF + idx] = xv;
    }
    g_xi[idx] = xv;
    sxi[ln][ch] = xv;
  }
  __syncthreads();
  const float* x = sxi[ln];
  float u = 0.f, v = b1m[ch];
  #pragma unroll
  for (int i = 0; i < 16; i++) {
    u += x[i] * sW[i * 64 + ch];
    v += x[i] * sW[(16 + i) * 64 + ch];
  }
  g_u[node * 64 + ch] = u;
  g_v[node * 64 + ch] = v;
}

// fused edge accumulation (warp per dst node, CSR) + node MLP -> k[s]
__global__ __launch_bounds__(256) void edge_node_kernel(
    int s, int it, int sub,
    const float* __restrict__ t,
    const float* __restrict__ W1m, const float* __restrict__ W2m,
    const float* __restrict__ b2m, const float* __restrict__ W1n,
    const float* __restrict__ W2n, const float* __restrict__ b2n)
{
  __shared__ float sWea[4 * 64];
  __shared__ float sW2m[64 * 16];
  __shared__ float sW1nx[16 * 64];
  __shared__ float sW1na[16 * 64];
  __shared__ float sW2n[64 * 16];
  __shared__ float swt[64];
  __shared__ float sb2m[16], sb2n[16];
  __shared__ float sbuf[8][64];
  __shared__ float sxi[8][16];
  __shared__ float sagg[8][16];

  int tid = threadIdx.x;
  for (int i = tid; i < 256; i += 256) sWea[i] = W1m[32 * 64 + i];
  for (int i = tid; i < 1024; i += 256) {
    sW2m[i]  = W2m[i];
    sW1nx[i] = W1n[i];
    sW1na[i] = W1n[1024 + i];
    sW2n[i]  = W2n[i];
  }
  if (tid < 64) swt[tid] = W1n[208 * 64 + tid];
  if (tid < 16) { sb2m[tid] = b2m[tid]; sb2n[tid] = b2n[tid]; }

  int w = tid >> 5, lane = tid & 31;
  int n = blockIdx.x * 8 + w;
  if (lane < 16) sxi[w][lane] = g_xi[n * 16 + lane];
  __syncthreads();

  float tA = t[it], tB = t[it + 1];
  float dti = (tB - tA) * 0.25f;
  float ti = tA + (float)sub * dti + c_C[s] * dti;

  float v0 = g_v[n * 64 + lane];
  float v1 = g_v[n * 64 + 32 + lane];
  float acc0 = 0.f, acc1 = 0.f;
  int beg = g_rowptr[n], end = g_rowptr[n + 1];
  for (int e = beg; e < end; e++) {
    int src = g_src_sorted[e];
    float4 ea = g_ea_sorted[e];
    const float* ub = &g_u[src * 64];
    float a0 = ub[lane] + v0;
    float a1 = ub[32 + lane] + v1;
    a0 += ea.x * sWea[lane]       + ea.y * sWea[64 + lane]
        + ea.z * sWea[128 + lane] + ea.w * sWea[192 + lane];
    a1 += ea.x * sWea[32 + lane]       + ea.y * sWea[64 + 32 + lane]
        + ea.z * sWea[128 + 32 + lane] + ea.w * sWea[192 + 32 + lane];
    acc0 += tanh_fast(a0);
    acc1 += tanh_fast(a1);
  }

  // agg16 = hsum @ W2m + deg*b2m
  sbuf[w][lane] = acc0;
  sbuf[w][32 + lane] = acc1;
  __syncwarp();
  int j = lane & 15;
  int cbase = (lane < 16) ? 0 : 32;
  float p = 0.f;
  #pragma unroll
  for (int c = 0; c < 32; c++) p += sbuf[w][cbase + c] * sW2m[(cbase + c) * 16 + j];
  p += __shfl_xor_sync(0xffffffffu, p, 16);
  float degf = (float)(end - beg);
  if (lane < 16) sagg[w][lane] = p + degf * sb2m[j];
  __syncwarp();

  // hidden = xi@W1n_x + agg@W1n_agg + aug_proj + ti*wt
  float h0 = g_augproj[n * 64 + lane]      + ti * swt[lane];
  float h1 = g_augproj[n * 64 + 32 + lane] + ti * swt[32 + lane];
  #pragma unroll
  for (int i = 0; i < 16; i++) {
    float xv = sxi[w][i], av = sagg[w][i];
    h0 += xv * sW1nx[i * 64 + lane]      + av * sW1na[i * 64 + lane];
    h1 += xv * sW1nx[i * 64 + 32 + lane] + av * sW1na[i * 64 + 32 + lane];
  }
  __syncwarp();
  sbuf[w][lane] = tanh_fast(h0);
  sbuf[w][32 + lane] = tanh_fast(h1);
  __syncwarp();

  float o = 0.f;
  #pragma unroll
  for (int c = 0; c < 32; c++) o += sbuf[w][cbase + c] * sW2n[(cbase + c) * 16 + j];
  o += __shfl_xor_sync(0xffffffffu, o, 16);
  if (lane < 16) g_k[s][n * 16 + j] = o + sb2n[j];
}

__global__ __launch_bounds__(256) void gather_out_kernel(
    const int* __restrict__ mask_idx, float* __restrict__ out)
{
  int idx = blockIdx.x * 256 + threadIdx.x;
  if (idx < TOUT * NF) {
    int row = idx / NF;
    int rem = idx - row * NF;
    out[idx] = g_ys[mask_idx[row] * NF + rem];
  }
}

// ---------------- launcher ----------------
extern "C" void kernel_launch(void* const* d_in, const int* in_sizes, int n_in,
                              void* d_out, int out_size)
{
  const float* x_hist   = (const float*)d_in[0];
  const float* x_mask   = (const float*)d_in[1];
  const int*   ei       = (const int*)d_in[2];
  const float* ea       = (const float*)d_in[3];
  const float* t        = (const float*)d_in[4];
  const int*   mask_idx = (const int*)d_in[5];
  const float* W1m = (const float*)d_in[6];
  const float* b1m = (const float*)d_in[7];
  const float* W2m = (const float*)d_in[8];
  const float* b2m = (const float*)d_in[9];
  const float* W1n = (const float*)d_in[10];
  const float* b1n = (const float*)d_in[11];
  const float* W2n = (const float*)d_in[12];
  const float* b2n = (const float*)d_in[13];
  float* out = (float*)d_out;

  // once-per-launch preprocessing (amortized over 240 evals)
  augproj_kernel<<<NN / 4, 256>>>(x_hist, x_mask, W1n, b1n);
  copyx0_kernel<<<(NF + 255) / 256, 256>>>(x_hist);
  zero_deg_kernel<<<(NN + 255) / 256, 256>>>();
  hist_kernel<<<(EE + 255) / 256, 256>>>(ei);
  scan_kernel<<<1, 1024>>>();
  scatter_kernel<<<(EE + 255) / 256, 256>>>(ei, ea);

  // initial u,v,xi from x0
  pre_kernel<<<NN / 8, 512>>>(t, 0, 0, -1, W1m, b1m);

  for (int it = 0; it < TOUT; it++) {
    for (int sub = 0; sub < 4; sub++) {
      for (int s = 0; s < 6; s++) {
        edge_node_kernel<<<NN / 8, 256>>>(s, it, sub, t, W1m, W2m, b2m, W1n, W2n, b2n);
        if (s < 5) pre_kernel<<<NN / 8, 512>>>(t, it, s + 1, -1, W1m, b1m);
      }
      int outrow = (sub == 3) ? it : -1;
      // final combine (B row): updates x0 in place, emits output row,
      // and produces u,v,xi for the next step's stage 0.
      pre_kernel<<<NN / 8, 512>>>(t, it, 6, outrow, W1m, b1m);
    }
  }

  gather_out_kernel<<<(TOUT * NF + 255) / 256, 256>>>(mask_idx, out);
}

// round 4
// speedup vs baseline: 1.1500x; 1.1473x over previous
#include <cuda_runtime.h>
#include <cuda_fp16.h>

#define NN 50000
#define FF 16
#define EE 800000
#define HH 64
#define TOUT 10
#define NF (NN*FF)

// ---------------- device state ----------------
__device__ float  g_x0[NF];
__device__ float  g_xi[NF];
__device__ float  g_k[6][NF];
__device__ __half2 g_uv[2][NN*32];   // packed u: (.x = ch lane, .y = ch lane+32), double-buffered
__device__ float  g_v[NN*HH];
__device__ float  g_augproj[NN*HH];
__device__ float  g_ys[TOUT*NF];
__device__ int    g_deg[NN];
__device__ int    g_rowptr[NN+1];
__device__ int    g_wptr[NN];
__device__ int    g_src_sorted[EE];
__device__ float4 g_ea_sorted[EE];

// DOPRI5 coefficients. Row 0 unused, rows 1..5 = A[0..4], row 6 = B.
__constant__ float c_coef[7][6] = {
  {0.f,0.f,0.f,0.f,0.f,0.f},
  {(float)(0.2), 0.f,0.f,0.f,0.f,0.f},
  {(float)(3.0/40.0), (float)(9.0/40.0), 0.f,0.f,0.f,0.f},
  {(float)(44.0/45.0), (float)(-56.0/15.0), (float)(32.0/9.0), 0.f,0.f,0.f},
  {(float)(19372.0/6561.0), (float)(-25360.0/2187.0), (float)(64448.0/6561.0), (float)(-212.0/729.0), 0.f,0.f},
  {(float)(9017.0/3168.0), (float)(-355.0/33.0), (float)(46732.0/5247.0), (float)(49.0/176.0), (float)(-5103.0/18656.0), 0.f},
  {(float)(35.0/384.0), 0.f, (float)(500.0/1113.0), (float)(125.0/192.0), (float)(-2187.0/6784.0), (float)(11.0/84.0)}
};
__constant__ float c_C[6] = {0.f, 0.2f, 0.3f, 0.8f, (float)(8.0/9.0), 1.f};

__device__ __forceinline__ float tanha(float x) {
  float r;
  asm("tanh.approx.f32 %0, %1;" : "=f"(r) : "f"(x));
  return r;
}

// ---------------- once-per-launch setup ----------------

__global__ __launch_bounds__(256) void augproj_kernel(
    const float* __restrict__ xh, const float* __restrict__ xm,
    const float* __restrict__ W1n, const float* __restrict__ b1n)
{
  __shared__ float saug[4][176];
  int tid = threadIdx.x;
  int ln = tid >> 6;
  int ch = tid & 63;
  int n = blockIdx.x * 4 + ln;
  if (ch < 16) {
    int f = ch;
    float xs[10], ms[10];
    float sm = 0.f, cm = 0.f;
    #pragma unroll
    for (int tt = 0; tt < 10; tt++) {
      xs[tt] = xh[(tt * NN + n) * FF + f];
      ms[tt] = xm[tt * NN + n];
      sm += xs[tt] * ms[tt];
      cm += ms[tt];
    }
    float cnt = fmaxf(cm, 1.0f);
    float mean = sm / cnt;
    float var = 0.f;
    #pragma unroll
    for (int tt = 0; tt < 10; tt++) { float d = xs[tt] - mean; var += d * d * ms[tt]; }
    var /= cnt;
    #pragma unroll
    for (int tt = 0; tt < 9; tt++)
      saug[ln][tt * 16 + f] = (xs[tt + 1] - xs[tt]) * (ms[tt + 1] * ms[tt]);
    saug[ln][144 + f] = mean;
    saug[ln][160 + f] = var;
  }
  __syncthreads();
  float acc = b1n[ch];
  #pragma unroll 8
  for (int r = 0; r < 176; r++)
    acc += saug[ln][r] * W1n[(32 + r) * 64 + ch];
  g_augproj[n * 64 + ch] = acc;
}

__global__ __launch_bounds__(256) void zero_deg_kernel() {
  int i = blockIdx.x * 256 + threadIdx.x;
  if (i < NN) g_deg[i] = 0;
}

__global__ __launch_bounds__(256) void hist_kernel(const int* __restrict__ ei) {
  int e = blockIdx.x * 256 + threadIdx.x;
  if (e < EE) atomicAdd(&g_deg[ei[EE + e]], 1);
}

__global__ __launch_bounds__(1024) void scan_kernel() {
  __shared__ int wsum[32];
  int tid = threadIdx.x, lane = tid & 31, wid = tid >> 5;
  int carry = 0;
  for (int base = 0; base < NN; base += 1024) {
    int i = base + tid;
    int v = (i < NN) ? g_deg[i] : 0;
    int x = v;
    #pragma unroll
    for (int o = 1; o < 32; o <<= 1) { int y = __shfl_up_sync(0xffffffffu, x, o); if (lane >= o) x += y; }
    if (lane == 31) wsum[wid] = x;
    __syncthreads();
    if (wid == 0) {
      int s = wsum[lane];
      #pragma unroll
      for (int o = 1; o < 32; o <<= 1) { int y = __shfl_up_sync(0xffffffffu, s, o); if (lane >= o) s += y; }
      wsum[lane] = s;
    }
    __syncthreads();
    int incl = x + carry + (wid > 0 ? wsum[wid - 1] : 0);
    if (i < NN) { g_rowptr[i + 1] = incl; g_wptr[i] = incl - v; }
    carry += wsum[31];
    __syncthreads();
  }
  if (tid == 0) g_rowptr[0] = 0;
}

__global__ __launch_bounds__(256) void scatter_kernel(
    const int* __restrict__ ei, const float* __restrict__ ea)
{
  int e = blockIdx.x * 256 + threadIdx.x;
  if (e < EE) {
    int d = ei[EE + e];
    int pos = atomicAdd(&g_wptr[d], 1);
    g_src_sorted[pos] = ei[e];
    g_ea_sorted[pos] = ((const float4*)ea)[e];
  }
}

// initial state: x0 = x_hist[-1], xi = x0, u/v projections into buffer 0
__global__ __launch_bounds__(256) void init_kernel(
    const float* __restrict__ xh,
    const float* __restrict__ W1m, const float* __restrict__ b1m)
{
  __shared__ float sW[32 * 64];
  __shared__ float sb[64];
  __shared__ float sxi[8][16];
  int tid = threadIdx.x;
  #pragma unroll
  for (int i = tid; i < 512; i += 256) ((float4*)sW)[i] = ((const float4*)W1m)[i];
  if (tid < 16) ((float4*)sb)[tid] = ((const float4*)b1m)[tid];
  int w = tid >> 5, lane = tid & 31;
  int n = blockIdx.x * 8 + w;
  if (lane < 16) {
    int idx = n * 16 + lane;
    float xv = xh[9 * NF + idx];
    g_x0[idx] = xv;
    g_xi[idx] = xv;
    sxi[w][lane] = xv;
  }
  __syncthreads();
  float u0 = 0.f, u1 = 0.f;
  float v0 = sb[lane], v1 = sb[32 + lane];
  #pragma unroll
  for (int i = 0; i < 16; i++) {
    float xv = sxi[w][i];
    u0 += xv * sW[i * 64 + lane];
    u1 += xv * sW[i * 64 + 32 + lane];
    v0 += xv * sW[(16 + i) * 64 + lane];
    v1 += xv * sW[(16 + i) * 64 + 32 + lane];
  }
  g_uv[0][n * 32 + lane] = __floats2half2_rn(u0, u1);
  g_v[n * 64 + lane] = v0;
  g_v[n * 64 + 32 + lane] = v1;
}

// ---------------- fused per-stage kernel ----------------
// warp per dst node: edge accumulate (CSR, u from half2 buffer pbuf) +
// node MLP -> k[s], then epilogue: xi_{s+1}, u/v projection into buffer pbuf^1.
__global__ __launch_bounds__(256) void edge_node_kernel(
    int s, int it, int sub, int outrow, int pbuf,
    const float* __restrict__ t,
    const float* __restrict__ W1m, const float* __restrict__ W2m,
    const float* __restrict__ b2m, const float* __restrict__ W1n,
    const float* __restrict__ W2n, const float* __restrict__ b2n,
    const float* __restrict__ b1m)
{
  __shared__ float sWea[4 * 64];
  __shared__ float sW2m[64 * 16];
  __shared__ float sW1nx[16 * 64];
  __shared__ float sW1na[16 * 64];
  __shared__ float sW2n[64 * 16];
  __shared__ float sW1m[32 * 64];
  __shared__ float swt[64];
  __shared__ float sb1m[64];
  __shared__ float sb2m[16], sb2n[16];
  __shared__ float sbuf[8][64];
  __shared__ float sxi[8][16];
  __shared__ float sagg[8][16];
  __shared__ float sxin[8][16];

  int tid = threadIdx.x;
  // stage weights (vectorized)
  if (tid < 64)  ((float4*)sWea)[tid] = ((const float4*)(W1m + 32 * 64))[tid];
  for (int i = tid; i < 256; i += 256) {
    ((float4*)sW2m)[i]  = ((const float4*)W2m)[i];
    ((float4*)sW1nx)[i] = ((const float4*)W1n)[i];
    ((float4*)sW1na)[i] = ((const float4*)(W1n + 1024))[i];
    ((float4*)sW2n)[i]  = ((const float4*)W2n)[i];
  }
  for (int i = tid; i < 512; i += 256) ((float4*)sW1m)[i] = ((const float4*)W1m)[i];
  if (tid < 16) ((float4*)swt)[tid]  = ((const float4*)(W1n + 208 * 64))[tid];
  if (tid >= 16 && tid < 32) ((float4*)sb1m)[tid - 16] = ((const float4*)b1m)[tid - 16];
  if (tid >= 32 && tid < 36) ((float4*)sb2m)[tid - 32] = ((const float4*)b2m)[tid - 32];
  if (tid >= 36 && tid < 40) ((float4*)sb2n)[tid - 36] = ((const float4*)b2n)[tid - 36];

  int w = tid >> 5, lane = tid & 31;
  int n = blockIdx.x * 8 + w;
  if (lane < 16) sxi[w][lane] = g_xi[n * 16 + lane];
  __syncthreads();

  float tA = t[it], tB = t[it + 1];
  float dti = (tB - tA) * 0.25f;
  float ti = tA + (float)sub * dti + c_C[s] * dti;

  const __half2* __restrict__ U = &g_uv[pbuf][0];
  float v0 = g_v[n * 64 + lane];
  float v1 = g_v[n * 64 + 32 + lane];
  float wx0 = sWea[lane],        wx1 = sWea[32 + lane];
  float wy0 = sWea[64 + lane],   wy1 = sWea[96 + lane];
  float wz0 = sWea[128 + lane],  wz1 = sWea[160 + lane];
  float ww0 = sWea[192 + lane],  ww1 = sWea[224 + lane];

  float acc0 = 0.f, acc1 = 0.f;
  int beg = g_rowptr[n], end = g_rowptr[n + 1];

  // 2-deep software pipeline over edges
  int e = beg;
  int srcc = 0; float4 eac = make_float4(0.f,0.f,0.f,0.f); __half2 uhc = __float2half2_rn(0.f);
  if (e < end) {
    srcc = g_src_sorted[e];
    eac  = g_ea_sorted[e];
    uhc  = U[srcc * 32 + lane];
  }
  for (; e < end; e++) {
    int e1 = e + 1;
    int srcn = srcc; float4 ean = eac; __half2 uhn = uhc;
    if (e1 < end) {
      srcn = g_src_sorted[e1];
      ean  = g_ea_sorted[e1];
      uhn  = U[srcn * 32 + lane];
    }
    float2 uf = __half22float2(uhc);
    float a0 = uf.x + v0;
    float a1 = uf.y + v1;
    a0 += eac.x * wx0 + eac.y * wy0 + eac.z * wz0 + eac.w * ww0;
    a1 += eac.x * wx1 + eac.y * wy1 + eac.z * wz1 + eac.w * ww1;
    acc0 += tanha(a0);
    acc1 += tanha(a1);
    srcc = srcn; eac = ean; uhc = uhn;
  }

  // agg16 = hsum @ W2m + deg*b2m
  sbuf[w][lane] = acc0;
  sbuf[w][32 + lane] = acc1;
  __syncwarp();
  int j = lane & 15;
  int cbase = (lane < 16) ? 0 : 32;
  float p = 0.f;
  #pragma unroll
  for (int c = 0; c < 32; c++) p += sbuf[w][cbase + c] * sW2m[(cbase + c) * 16 + j];
  p += __shfl_xor_sync(0xffffffffu, p, 16);
  float degf = (float)(end - beg);
  if (lane < 16) sagg[w][lane] = p + degf * sb2m[j];
  __syncwarp();

  // hidden = xi@W1n_x + agg@W1n_agg + aug_proj + ti*wt
  float h0 = g_augproj[n * 64 + lane]      + ti * swt[lane];
  float h1 = g_augproj[n * 64 + 32 + lane] + ti * swt[32 + lane];
  #pragma unroll
  for (int i = 0; i < 16; i++) {
    float xv = sxi[w][i], av = sagg[w][i];
    h0 += xv * sW1nx[i * 64 + lane]      + av * sW1na[i * 64 + lane];
    h1 += xv * sW1nx[i * 64 + 32 + lane] + av * sW1na[i * 64 + 32 + lane];
  }
  __syncwarp();
  sbuf[w][lane] = tanha(h0);
  sbuf[w][32 + lane] = tanha(h1);
  __syncwarp();

  float o = 0.f;
  #pragma unroll
  for (int c = 0; c < 32; c++) o += sbuf[w][cbase + c] * sW2n[(cbase + c) * 16 + j];
  o += __shfl_xor_sync(0xffffffffu, o, 16);
  float kval = o + sb2n[j];   // replicated on lane and lane+16

  // ---- fused epilogue: xi_{s+1} combine + u/v projection (buffer pbuf^1) ----
  if (lane < 16) {
    int idx = n * 16 + j;
    g_k[s][idx] = kval;
    int row = (s < 5) ? s + 1 : 6;
    float acc = c_coef[row][s] * kval;
    #pragma unroll
    for (int jj = 0; jj < 5; jj++) {
      if (jj < s) acc += c_coef[row][jj] * g_k[jj][idx];
    }
    float xv = g_x0[idx] + dti * acc;
    if (s == 5) {
      g_x0[idx] = xv;
      if (outrow >= 0) g_ys[outrow * NF + idx] = xv;
    }
    g_xi[idx] = xv;
    sxin[w][j] = xv;
  }
  __syncwarp();

  float u0 = 0.f, u1 = 0.f;
  float nv0 = sb1m[lane], nv1 = sb1m[32 + lane];
  #pragma unroll
  for (int i = 0; i < 16; i++) {
    float xv = sxin[w][i];
    u0  += xv * sW1m[i * 64 + lane];
    u1  += xv * sW1m[i * 64 + 32 + lane];
    nv0 += xv * sW1m[(16 + i) * 64 + lane];
    nv1 += xv * sW1m[(16 + i) * 64 + 32 + lane];
  }
  g_uv[pbuf ^ 1][n * 32 + lane] = __floats2half2_rn(u0, u1);
  g_v[n * 64 + lane] = nv0;
  g_v[n * 64 + 32 + lane] = nv1;
}

__global__ __launch_bounds__(256) void gather_out_kernel(
    const int* __restrict__ mask_idx, float* __restrict__ out)
{
  int idx = blockIdx.x * 256 + threadIdx.x;
  if (idx < TOUT * NF) {
    int row = idx / NF;
    int rem = idx - row * NF;
    out[idx] = g_ys[mask_idx[row] * NF + rem];
  }
}

// ---------------- launcher ----------------
extern "C" void kernel_launch(void* const* d_in, const int* in_sizes, int n_in,
                              void* d_out, int out_size)
{
  const float* x_hist   = (const float*)d_in[0];
  const float* x_mask   = (const float*)d_in[1];
  const int*   ei       = (const int*)d_in[2];
  const float* ea       = (const float*)d_in[3];
  const float* t        = (const float*)d_in[4];
  const int*   mask_idx = (const int*)d_in[5];
  const float* W1m = (const float*)d_in[6];
  const float* b1m = (const float*)d_in[7];
  const float* W2m = (const float*)d_in[8];
  const float* b2m = (const float*)d_in[9];
  const float* W1n = (const float*)d_in[10];
  const float* b1n = (const float*)d_in[11];
  const float* W2n = (const float*)d_in[12];
  const float* b2n = (const float*)d_in[13];
  float* out = (float*)d_out;

  // once-per-launch preprocessing
  augproj_kernel<<<NN / 4, 256>>>(x_hist, x_mask, W1n, b1n);
  zero_deg_kernel<<<(NN + 255) / 256, 256>>>();
  hist_kernel<<<(EE + 255) / 256, 256>>>(ei);
  scan_kernel<<<1, 1024>>>();
  scatter_kernel<<<(EE + 255) / 256, 256>>>(ei, ea);
  init_kernel<<<NN / 8, 256>>>(x_hist, W1m, b1m);

  int L = 0;
  for (int it = 0; it < TOUT; it++) {
    for (int sub = 0; sub < 4; sub++) {
      for (int s = 0; s < 6; s++) {
        int outrow = (s == 5 && sub == 3) ? it : -1;
        edge_node_kernel<<<NN / 8, 256>>>(s, it, sub, outrow, L & 1,
                                          t, W1m, W2m, b2m, W1n, W2n, b2n, b1m);
        L++;
      }
    }
  }

  gather_out_kernel<<<(TOUT * NF + 255) / 256, 256>>>(mask_idx, out);
}